// round 6
// baseline (speedup 1.0000x reference)
#include <cuda_runtime.h>
#include <cstdint>

// ---------------------------------------------------------------------------
// ManifoldMatchingLoss:
//   A_f = log_softmax(-pdist(image_flat) * exp(T), axis=1)   (128x128)
//   A_g = log_softmax(-pdist(lang_flat)  * exp(T), axis=1)   (128x128)
//   out[j] = sum_i exp(A_g[i,j]) * (A_g[i,j] - A_f[i,j])     (128,)
//
// Strategy: split-K Gram matrices (deterministic partial buffers, no float
// atomics), then norms -> rows (softmax+KL) -> column sum. 4 launches, all
// graph-capturable, allocation-free (scratch in __device__ globals).
// ---------------------------------------------------------------------------

#define B_N   128
#define D_F   8192          // image: 64*128
#define D_G   4096          // lang:  32*128
#define CK    64            // K-chunk per split block
#define S_F   (D_F / CK)    // 128 splits for image
#define S_G   (D_G / CK)    // 64 splits for lang
#define KSTEP 16
#define SM_PAD 132          // 128 + 4 pad (16B-aligned rows, fewer conflicts)

__device__ float g_GfPart[S_F * B_N * B_N];   // 8 MB
__device__ float g_GgPart[S_G * B_N * B_N];   // 4 MB
__device__ float g_normF[B_N];
__device__ float g_normG[B_N];
__device__ float g_kl[B_N * B_N];

// ---- packed f32x2 helpers (Blackwell FFMA2 path; 2 FMA per issue) ----------
__device__ __forceinline__ unsigned long long pack2(float lo, float hi) {
    unsigned long long r;
    asm("mov.b64 %0, {%1, %2};" : "=l"(r) : "f"(lo), "f"(hi));
    return r;
}
__device__ __forceinline__ float2 unpack2(unsigned long long v) {
    float2 r;
    asm("mov.b64 {%0, %1}, %2;" : "=f"(r.x), "=f"(r.y) : "l"(v));
    return r;
}
__device__ __forceinline__ void ffma2(unsigned long long& d,
                                      unsigned long long a,
                                      unsigned long long b) {
    asm("fma.rn.f32x2 %0, %1, %2, %0;" : "+l"(d) : "l"(a), "l"(b));
}

// ---------------------------------------------------------------------------
// Kernel 1: split-K Gram. Each block handles one (tensor, split). Tile is the
// FULL 128x128 output; A-tile == B-tile (same matrix), so one SMEM buffer.
// 256 threads, 8x8 microtile per thread (i in {4ty..4ty+3, 64+4ty..+3}, same
// for j with tx) -> conflict-light float4 LDS.
// ---------------------------------------------------------------------------
__global__ __launch_bounds__(256, 2)
void gram_kernel(const float* __restrict__ Fm, const float* __restrict__ Gm) {
    __shared__ __align__(16) float As[KSTEP][SM_PAD];

    const int bx = blockIdx.x;
    const float* src;
    int D, split;
    float* part;
    if (bx < S_F) {
        split = bx;         src = Fm; D = D_F;
        part = g_GfPart + (size_t)split * (B_N * B_N);
    } else {
        split = bx - S_F;   src = Gm; D = D_G;
        part = g_GgPart + (size_t)split * (B_N * B_N);
    }
    const int k0base = split * CK;

    const int t  = threadIdx.x;
    const int tx = t & 15;
    const int ty = t >> 4;
    const int lr = t >> 2;   // load row (0..63); second row = lr+64
    const int lq = t & 3;    // float4 quad within the 16-wide K step

    unsigned long long acc[8][4];
#pragma unroll
    for (int u = 0; u < 8; u++)
#pragma unroll
        for (int v = 0; v < 4; v++) acc[u][v] = 0ull;

    const float* p0 = src + (size_t)lr * D + k0base + lq * 4;
    const float* p1 = src + (size_t)(lr + 64) * D + k0base + lq * 4;

    for (int kc = 0; kc < CK; kc += KSTEP) {
        float4 v0 = *(const float4*)(p0 + kc);
        float4 v1 = *(const float4*)(p1 + kc);
        __syncthreads();   // previous iteration's reads complete
        As[lq * 4 + 0][lr] = v0.x;
        As[lq * 4 + 1][lr] = v0.y;
        As[lq * 4 + 2][lr] = v0.z;
        As[lq * 4 + 3][lr] = v0.w;
        As[lq * 4 + 0][lr + 64] = v1.x;
        As[lq * 4 + 1][lr + 64] = v1.y;
        As[lq * 4 + 2][lr + 64] = v1.z;
        As[lq * 4 + 3][lr + 64] = v1.w;
        __syncthreads();

#pragma unroll
        for (int k = 0; k < KSTEP; k++) {
            float4 a0 = *(const float4*)&As[k][ty * 4];
            float4 a1 = *(const float4*)&As[k][64 + ty * 4];
            float4 b0 = *(const float4*)&As[k][tx * 4];
            float4 b1 = *(const float4*)&As[k][64 + tx * 4];

            unsigned long long bb0 = pack2(b0.x, b0.y);
            unsigned long long bb1 = pack2(b0.z, b0.w);
            unsigned long long bb2 = pack2(b1.x, b1.y);
            unsigned long long bb3 = pack2(b1.z, b1.w);

            float av[8] = {a0.x, a0.y, a0.z, a0.w, a1.x, a1.y, a1.z, a1.w};
#pragma unroll
            for (int u = 0; u < 8; u++) {
                unsigned long long ap = pack2(av[u], av[u]);
                ffma2(acc[u][0], ap, bb0);
                ffma2(acc[u][1], ap, bb1);
                ffma2(acc[u][2], ap, bb2);
                ffma2(acc[u][3], ap, bb3);
            }
        }
    }

    // epilogue: coalesced float4 stores into this split's partial buffer
#pragma unroll
    for (int u = 0; u < 8; u++) {
        int i = (u < 4) ? (ty * 4 + u) : (64 + ty * 4 + (u - 4));
        float2 c0 = unpack2(acc[u][0]);
        float2 c1 = unpack2(acc[u][1]);
        float2 c2 = unpack2(acc[u][2]);
        float2 c3 = unpack2(acc[u][3]);
        float4 w0 = make_float4(c0.x, c0.y, c1.x, c1.y);
        float4 w1 = make_float4(c2.x, c2.y, c3.x, c3.y);
        *(float4*)(part + i * B_N + tx * 4)      = w0;
        *(float4*)(part + i * B_N + 64 + tx * 4) = w1;
    }
}

// ---------------------------------------------------------------------------
// Kernel 2: diagonal norms. Summation order MUST match rows_kernel's partial
// sum (single accumulator, ascending s) so sq_ii cancels to exactly 0.
// ---------------------------------------------------------------------------
__global__ void norms_kernel() {
    int j = threadIdx.x;
    float nf = 0.f;
    for (int s = 0; s < S_F; s++) nf += g_GfPart[s * (B_N * B_N) + j * (B_N + 1)];
    float ng = 0.f;
    for (int s = 0; s < S_G; s++) ng += g_GgPart[s * (B_N * B_N) + j * (B_N + 1)];
    g_normF[j] = nf;
    g_normG[j] = ng;
}

// ---- fixed-order block reduction over 128 threads (4 warps) ---------------
__device__ __forceinline__ float blkReduce(float v, bool domax, float* sb) {
#pragma unroll
    for (int o = 16; o > 0; o >>= 1) {
        float other = __shfl_xor_sync(0xffffffffu, v, o);
        v = domax ? fmaxf(v, other) : (v + other);
    }
    if ((threadIdx.x & 31) == 0) sb[threadIdx.x >> 5] = v;
    __syncthreads();
    float r;
    if (domax) r = fmaxf(fmaxf(sb[0], sb[1]), fmaxf(sb[2], sb[3]));
    else       r = (sb[0] + sb[1]) + (sb[2] + sb[3]);
    __syncthreads();
    return r;
}

// ---------------------------------------------------------------------------
// Kernel 3: one block per row i. Sum split-K partials, distances, row-wise
// log-softmax for both tensors, KL element -> scratch.
// ---------------------------------------------------------------------------
__global__ __launch_bounds__(128)
void rows_kernel(const float* __restrict__ tptr) {
    __shared__ float sb[4];
    const int i = blockIdx.x;
    const int j = threadIdx.x;
    const float eT = expf(tptr[0]);

    float gf = 0.f;
    for (int s = 0; s < S_F; s++) gf += g_GfPart[s * (B_N * B_N) + i * B_N + j];
    float gg = 0.f;
    for (int s = 0; s < S_G; s++) gg += g_GgPart[s * (B_N * B_N) + i * B_N + j];

    const float nfi = g_normF[i], nfj = g_normF[j];
    const float ngi = g_normG[i], ngj = g_normG[j];

    float sqf = (nfi + nfj) - 2.0f * gf;   // exactly 0 on the diagonal
    float sqg = (ngi + ngj) - 2.0f * gg;
    float df = (sqf > 0.f) ? sqrtf(sqf) : 0.f;
    float dg = (sqg > 0.f) ? sqrtf(sqg) : 0.f;
    float pf = -df * eT;
    float pg = -dg * eT;

    float mf = blkReduce(pf, true, sb);
    float sf = blkReduce(expf(pf - mf), false, sb);
    float mg = blkReduce(pg, true, sb);
    float sg = blkReduce(expf(pg - mg), false, sb);

    float af = pf - (mf + logf(sf));
    float ag = pg - (mg + logf(sg));

    g_kl[i * B_N + j] = expf(ag) * (ag - af);
}

// ---------------------------------------------------------------------------
// Kernel 4: deterministic column sum -> out (128 floats)
// ---------------------------------------------------------------------------
__global__ void colsum_kernel(float* __restrict__ out) {
    int j = threadIdx.x;
    float s = 0.f;
    for (int i = 0; i < B_N; i++) s += g_kl[i * B_N + j];
    out[j] = s;
}

// ---------------------------------------------------------------------------
extern "C" void kernel_launch(void* const* d_in, const int* in_sizes, int n_in,
                              void* d_out, int out_size) {
    const float* img = nullptr;
    const float* lng = nullptr;
    const float* tmp = nullptr;
    for (int i = 0; i < n_in; i++) {
        if (in_sizes[i] == B_N * D_F)      img = (const float*)d_in[i];
        else if (in_sizes[i] == B_N * D_G) lng = (const float*)d_in[i];
        else if (in_sizes[i] == 1)         tmp = (const float*)d_in[i];
    }
    if (!img) img = (const float*)d_in[0];
    if (!lng) lng = (const float*)d_in[1];
    if (!tmp) tmp = (const float*)d_in[2];

    gram_kernel<<<S_F + S_G, 256>>>(img, lng);
    norms_kernel<<<1, B_N>>>();
    rows_kernel<<<B_N, B_N>>>(tmp);
    colsum_kernel<<<1, B_N>>>((float*)d_out);
}

// round 7
// speedup vs baseline: 1.6291x; 1.6291x over previous
#include <cuda_runtime.h>
#include <cstdint>

// ---------------------------------------------------------------------------
// ManifoldMatchingLoss:
//   A_f = log_softmax(-pdist(image_flat) * exp(T), axis=1)   (128x128)
//   A_g = log_softmax(-pdist(lang_flat)  * exp(T), axis=1)   (128x128)
//   out[j] = sum_i exp(A_g[i,j]) * (A_g[i,j] - A_f[i,j])     (128,)
//
// 3 launches: split-K Gram (+diag side-channel) -> rows (norms+softmax+KL)
// -> parallel deterministic column sum. All graph-capturable, allocation-free.
// ---------------------------------------------------------------------------

#define B_N   128
#define D_F   8192          // image: 64*128
#define D_G   4096          // lang:  32*128
#define CK    64            // K-chunk per split block
#define S_F   (D_F / CK)    // 128 splits for image
#define S_G   (D_G / CK)    // 64 splits for lang
#define KSTEP 16
#define SM_PAD 132

__device__ float g_GfPart[S_F * B_N * B_N];   // 8 MB
__device__ float g_GgPart[S_G * B_N * B_N];   // 4 MB
__device__ float g_diagF[S_F * B_N];          // per-split diagonal (coalesced)
__device__ float g_diagG[S_G * B_N];
__device__ float g_kl[B_N * B_N];

// ---- packed f32x2 helpers (Blackwell FFMA2 path; 2 FMA per issue) ----------
__device__ __forceinline__ unsigned long long pack2(float lo, float hi) {
    unsigned long long r;
    asm("mov.b64 %0, {%1, %2};" : "=l"(r) : "f"(lo), "f"(hi));
    return r;
}
__device__ __forceinline__ float2 unpack2(unsigned long long v) {
    float2 r;
    asm("mov.b64 {%0, %1}, %2;" : "=f"(r.x), "=f"(r.y) : "l"(v));
    return r;
}
__device__ __forceinline__ void ffma2(unsigned long long& d,
                                      unsigned long long a,
                                      unsigned long long b) {
    asm("fma.rn.f32x2 %0, %1, %2, %0;" : "+l"(d) : "l"(a), "l"(b));
}

// ---------------------------------------------------------------------------
// Kernel 1: split-K Gram. One block per (tensor, split). Full 128x128 tile,
// A-tile == B-tile (Gram) -> single SMEM buffer. 256 thr, 8x8 microtile.
// Epilogue also emits the partial diagonal to a compact coalesced buffer.
// ---------------------------------------------------------------------------
__global__ __launch_bounds__(256, 2)
void gram_kernel(const float* __restrict__ Fm, const float* __restrict__ Gm) {
    __shared__ __align__(16) float As[KSTEP][SM_PAD];

    const int bx = blockIdx.x;
    const float* src;
    int D, split;
    float* part;
    float* diag;
    if (bx < S_F) {
        split = bx;         src = Fm; D = D_F;
        part = g_GfPart + (size_t)split * (B_N * B_N);
        diag = g_diagF + split * B_N;
    } else {
        split = bx - S_F;   src = Gm; D = D_G;
        part = g_GgPart + (size_t)split * (B_N * B_N);
        diag = g_diagG + split * B_N;
    }
    const int k0base = split * CK;

    const int t  = threadIdx.x;
    const int tx = t & 15;
    const int ty = t >> 4;
    const int lr = t >> 2;   // load row (0..63); second row = lr+64
    const int lq = t & 3;    // float4 quad within the 16-wide K step

    unsigned long long acc[8][4];
#pragma unroll
    for (int u = 0; u < 8; u++)
#pragma unroll
        for (int v = 0; v < 4; v++) acc[u][v] = 0ull;

    const float* p0 = src + (size_t)lr * D + k0base + lq * 4;
    const float* p1 = src + (size_t)(lr + 64) * D + k0base + lq * 4;

    for (int kc = 0; kc < CK; kc += KSTEP) {
        float4 v0 = *(const float4*)(p0 + kc);
        float4 v1 = *(const float4*)(p1 + kc);
        __syncthreads();
        As[lq * 4 + 0][lr] = v0.x;
        As[lq * 4 + 1][lr] = v0.y;
        As[lq * 4 + 2][lr] = v0.z;
        As[lq * 4 + 3][lr] = v0.w;
        As[lq * 4 + 0][lr + 64] = v1.x;
        As[lq * 4 + 1][lr + 64] = v1.y;
        As[lq * 4 + 2][lr + 64] = v1.z;
        As[lq * 4 + 3][lr + 64] = v1.w;
        __syncthreads();

#pragma unroll
        for (int k = 0; k < KSTEP; k++) {
            float4 a0 = *(const float4*)&As[k][ty * 4];
            float4 a1 = *(const float4*)&As[k][64 + ty * 4];
            float4 b0 = *(const float4*)&As[k][tx * 4];
            float4 b1 = *(const float4*)&As[k][64 + tx * 4];

            unsigned long long bb0 = pack2(b0.x, b0.y);
            unsigned long long bb1 = pack2(b0.z, b0.w);
            unsigned long long bb2 = pack2(b1.x, b1.y);
            unsigned long long bb3 = pack2(b1.z, b1.w);

            float av[8] = {a0.x, a0.y, a0.z, a0.w, a1.x, a1.y, a1.z, a1.w};
#pragma unroll
            for (int u = 0; u < 8; u++) {
                unsigned long long ap = pack2(av[u], av[u]);
                ffma2(acc[u][0], ap, bb0);
                ffma2(acc[u][1], ap, bb1);
                ffma2(acc[u][2], ap, bb2);
                ffma2(acc[u][3], ap, bb3);
            }
        }
    }

    // epilogue: coalesced float4 stores of the partial tile
#pragma unroll
    for (int u = 0; u < 8; u++) {
        int i = (u < 4) ? (ty * 4 + u) : (64 + ty * 4 + (u - 4));
        float2 c0 = unpack2(acc[u][0]);
        float2 c1 = unpack2(acc[u][1]);
        float2 c2 = unpack2(acc[u][2]);
        float2 c3 = unpack2(acc[u][3]);
        float4 w0 = make_float4(c0.x, c0.y, c1.x, c1.y);
        float4 w1 = make_float4(c2.x, c2.y, c3.x, c3.y);
        *(float4*)(part + i * B_N + tx * 4)      = w0;
        *(float4*)(part + i * B_N + 64 + tx * 4) = w1;
    }

    // diagonal side-channel: threads on the tile diagonal (tx == ty) hold
    // 8 diagonal elements each; identical register values to the tile store,
    // so downstream norm sums cancel the diagonal bit-exactly.
    if (tx == ty) {
#pragma unroll
        for (int u = 0; u < 8; u++) {
            int i;
            float dval;
            if (u < 4) {
                i = ty * 4 + u;
                float2 p = unpack2(acc[u][u >> 1]);
                dval = (u & 1) ? p.y : p.x;
            } else {
                int w = u - 4;
                i = 64 + ty * 4 + w;
                float2 p = unpack2(acc[u][2 + (w >> 1)]);
                dval = (w & 1) ? p.y : p.x;
            }
            diag[i] = dval;
        }
    }
}

// ---- fixed-order block reduction over 128 threads (4 warps) ---------------
__device__ __forceinline__ float blkReduce(float v, bool domax, float* sb) {
#pragma unroll
    for (int o = 16; o > 0; o >>= 1) {
        float other = __shfl_xor_sync(0xffffffffu, v, o);
        v = domax ? fmaxf(v, other) : (v + other);
    }
    if ((threadIdx.x & 31) == 0) sb[threadIdx.x >> 5] = v;
    __syncthreads();
    float r;
    if (domax) r = fmaxf(fmaxf(sb[0], sb[1]), fmaxf(sb[2], sb[3]));
    else       r = (sb[0] + sb[1]) + (sb[2] + sb[3]);
    __syncthreads();
    return r;
}

// ---------------------------------------------------------------------------
// Kernel 2: one block per row i. Norms from the diag side-channel (coalesced,
// same add order as the gf/gg partial sums -> exact-zero diagonal), then sum
// split-K partials, distances, log-softmax for both tensors, KL -> scratch.
// ---------------------------------------------------------------------------
__global__ __launch_bounds__(128)
void rows_kernel(const float* __restrict__ tptr) {
    __shared__ float sb[4];
    __shared__ float sNF[B_N];
    __shared__ float sNG[B_N];
    const int i = blockIdx.x;
    const int j = threadIdx.x;
    const float eT = expf(tptr[0]);

    // norms for column j (ascending s, single accumulator)
    float nfj = 0.f;
#pragma unroll 8
    for (int s = 0; s < S_F; s++) nfj += g_diagF[s * B_N + j];
    float ngj = 0.f;
#pragma unroll 8
    for (int s = 0; s < S_G; s++) ngj += g_diagG[s * B_N + j];
    sNF[j] = nfj;
    sNG[j] = ngj;

    // gram entries (i, j): same ascending-s single-accumulator order
    float gf = 0.f;
#pragma unroll 8
    for (int s = 0; s < S_F; s++) gf += g_GfPart[s * (B_N * B_N) + i * B_N + j];
    float gg = 0.f;
#pragma unroll 8
    for (int s = 0; s < S_G; s++) gg += g_GgPart[s * (B_N * B_N) + i * B_N + j];

    __syncthreads();
    const float nfi = sNF[i];
    const float ngi = sNG[i];

    float sqf = (nfi + nfj) - 2.0f * gf;   // exactly 0 on the diagonal
    float sqg = (ngi + ngj) - 2.0f * gg;
    float df = (sqf > 0.f) ? sqrtf(sqf) : 0.f;
    float dg = (sqg > 0.f) ? sqrtf(sqg) : 0.f;
    float pf = -df * eT;
    float pg = -dg * eT;

    float mf = blkReduce(pf, true, sb);
    float sf = blkReduce(expf(pf - mf), false, sb);
    float mg = blkReduce(pg, true, sb);
    float sg = blkReduce(expf(pg - mg), false, sb);

    float af = pf - (mf + logf(sf));
    float ag = pg - (mg + logf(sg));

    g_kl[i * B_N + j] = expf(ag) * (ag - af);
}

// ---------------------------------------------------------------------------
// Kernel 3: deterministic column sum -> out. 1024 threads: 8 row-groups of 16
// rows each, then fixed-order 8-way reduce per column.
// ---------------------------------------------------------------------------
__global__ __launch_bounds__(1024)
void colsum_kernel(float* __restrict__ out) {
    __shared__ float sp[8][B_N];
    const int j = threadIdx.x & 127;
    const int r = threadIdx.x >> 7;          // 0..7

    float s = 0.f;
#pragma unroll
    for (int k = 0; k < 16; k++)
        s += g_kl[(r * 16 + k) * B_N + j];
    sp[r][j] = s;
    __syncthreads();

    if (threadIdx.x < B_N) {
        float acc = 0.f;
#pragma unroll
        for (int r2 = 0; r2 < 8; r2++) acc += sp[r2][j];
        out[j] = acc;
    }
}

// ---------------------------------------------------------------------------
extern "C" void kernel_launch(void* const* d_in, const int* in_sizes, int n_in,
                              void* d_out, int out_size) {
    const float* img = nullptr;
    const float* lng = nullptr;
    const float* tmp = nullptr;
    for (int i = 0; i < n_in; i++) {
        if (in_sizes[i] == B_N * D_F)      img = (const float*)d_in[i];
        else if (in_sizes[i] == B_N * D_G) lng = (const float*)d_in[i];
        else if (in_sizes[i] == 1)         tmp = (const float*)d_in[i];
    }
    if (!img) img = (const float*)d_in[0];
    if (!lng) lng = (const float*)d_in[1];
    if (!tmp) tmp = (const float*)d_in[2];

    gram_kernel<<<S_F + S_G, 256>>>(img, lng);
    rows_kernel<<<B_N, B_N>>>(tmp);
    colsum_kernel<<<1, 1024>>>((float*)d_out);
}

// round 8
// speedup vs baseline: 2.2222x; 1.3641x over previous
#include <cuda_runtime.h>
#include <cstdint>

// ---------------------------------------------------------------------------
// ManifoldMatchingLoss, 4 launches:
//   1) gram_kernel   : split-K Gram partials (FFMA2, pack-free inner loop)
//   2) reduce_kernel : partials -> final Gf, Gg (wide, deterministic)
//   3) rows_kernel   : dist -> log_softmax -> KL elements (norms = diag(G))
//   4) colsum_kernel : deterministic column sum -> out (128,)
// All graph-capturable, allocation-free.
// ---------------------------------------------------------------------------

#define B_N   128
#define D_F   8192          // image: 64*128
#define D_G   4096          // lang:  32*128
#define CK    64            // K-chunk per split block
#define S_F   (D_F / CK)    // 128 splits for image
#define S_G   (D_G / CK)    // 64 splits for lang
#define KSTEP 16

__device__ float g_GfPart[S_F * B_N * B_N];   // 8 MB
__device__ float g_GgPart[S_G * B_N * B_N];   // 4 MB
__device__ float g_Gf[B_N * B_N];             // final Gram (image)
__device__ float g_Gg[B_N * B_N];             // final Gram (lang)
__device__ float g_kl[B_N * B_N];

// ---- packed f32x2 helpers ---------------------------------------------------
__device__ __forceinline__ unsigned long long pack2(float lo, float hi) {
    unsigned long long r;
    asm("mov.b64 %0, {%1, %2};" : "=l"(r) : "f"(lo), "f"(hi));
    return r;
}
__device__ __forceinline__ float2 unpack2(unsigned long long v) {
    float2 r;
    asm("mov.b64 {%0, %1}, %2;" : "=f"(r.x), "=f"(r.y) : "l"(v));
    return r;
}
__device__ __forceinline__ void ffma2(unsigned long long& d,
                                      unsigned long long a,
                                      unsigned long long b) {
    asm("fma.rn.f32x2 %0, %1, %2, %0;" : "+l"(d) : "l"(a), "l"(b));
}

// ---------------------------------------------------------------------------
// Kernel 1: split-K Gram. One block per (tensor, split). Full 128x128 tile.
// Pack-free inner loop:
//   - B operand pairs loaded directly as ld.shared.v2.b64 from plain As
//   - A splats loaded as ld.shared.b64 from a duplicated (v,v) array Ad
// ---------------------------------------------------------------------------
__global__ __launch_bounds__(256, 2)
void gram_kernel(const float* __restrict__ Fm, const float* __restrict__ Gm) {
    __shared__ __align__(16) float As[KSTEP][132];                 // plain
    __shared__ __align__(16) unsigned long long Ad[KSTEP][133];    // (v,v) splat

    const int bx = blockIdx.x;
    const float* src;
    int D, split;
    float* part;
    if (bx < S_F) {
        split = bx;         src = Fm; D = D_F;
        part = g_GfPart + (size_t)split * (B_N * B_N);
    } else {
        split = bx - S_F;   src = Gm; D = D_G;
        part = g_GgPart + (size_t)split * (B_N * B_N);
    }
    const int k0base = split * CK;

    const int t  = threadIdx.x;
    const int tx = t & 15;
    const int ty = t >> 4;
    const int lr = t >> 2;   // load row (0..63); second row = lr+64
    const int lq = t & 3;    // which float4 quad of the 16-wide K step

    unsigned long long acc[8][4];
#pragma unroll
    for (int u = 0; u < 8; u++)
#pragma unroll
        for (int v = 0; v < 4; v++) acc[u][v] = 0ull;

    const float* p0 = src + (size_t)lr * D + k0base + lq * 4;
    const float* p1 = src + (size_t)(lr + 64) * D + k0base + lq * 4;

    float4 v0 = *(const float4*)(p0);
    float4 v1 = *(const float4*)(p1);

    for (int kc = 0; kc < CK; kc += KSTEP) {
        __syncthreads();   // previous iteration's smem reads complete
        {
            float a[4] = {v0.x, v0.y, v0.z, v0.w};
            float b[4] = {v1.x, v1.y, v1.z, v1.w};
#pragma unroll
            for (int q = 0; q < 4; q++) {
                As[lq * 4 + q][lr]      = a[q];
                As[lq * 4 + q][lr + 64] = b[q];
                Ad[lq * 4 + q][lr]      = pack2(a[q], a[q]);
                Ad[lq * 4 + q][lr + 64] = pack2(b[q], b[q]);
            }
        }
        __syncthreads();

        // register prefetch of next chunk (hidden under compute)
        if (kc + KSTEP < CK) {
            v0 = *(const float4*)(p0 + kc + KSTEP);
            v1 = *(const float4*)(p1 + kc + KSTEP);
        }

#pragma unroll
        for (int k = 0; k < KSTEP; k++) {
            // B pairs: columns (4tx,4tx+1),(4tx+2,4tx+3),(64+4tx,...)
            ulonglong2 lb0 = *(const ulonglong2*)&As[k][tx * 4];
            ulonglong2 lb1 = *(const ulonglong2*)&As[k][64 + tx * 4];

            unsigned long long aa[8];
#pragma unroll
            for (int u = 0; u < 4; u++) aa[u]     = Ad[k][ty * 4 + u];
#pragma unroll
            for (int u = 0; u < 4; u++) aa[4 + u] = Ad[k][64 + ty * 4 + u];

#pragma unroll
            for (int u = 0; u < 8; u++) {
                ffma2(acc[u][0], aa[u], lb0.x);
                ffma2(acc[u][1], aa[u], lb0.y);
                ffma2(acc[u][2], aa[u], lb1.x);
                ffma2(acc[u][3], aa[u], lb1.y);
            }
        }
    }

    // epilogue: coalesced float4 stores of the partial tile
#pragma unroll
    for (int u = 0; u < 8; u++) {
        int i = (u < 4) ? (ty * 4 + u) : (64 + ty * 4 + (u - 4));
        float2 c0 = unpack2(acc[u][0]);
        float2 c1 = unpack2(acc[u][1]);
        float2 c2 = unpack2(acc[u][2]);
        float2 c3 = unpack2(acc[u][3]);
        float4 w0 = make_float4(c0.x, c0.y, c1.x, c1.y);
        float4 w1 = make_float4(c2.x, c2.y, c3.x, c3.y);
        *(float4*)(part + i * B_N + tx * 4)      = w0;
        *(float4*)(part + i * B_N + 64 + tx * 4) = w1;
    }
}

// ---------------------------------------------------------------------------
// Kernel 2: wide deterministic split reduction -> final Gf, Gg.
// Blocks 0..63 : F, 256 elems/block, 4 threads/elem (each sums 32 splits)
// Blocks 64..95: G, 512 elems/block, 2 threads/elem (each sums 32 splits)
// Fixed grouping + fixed combine order -> deterministic.
// ---------------------------------------------------------------------------
__global__ __launch_bounds__(1024)
void reduce_kernel() {
    __shared__ float sp[4 * 256];   // 4KB, reused by both halves
    const int b = blockIdx.x;
    const int t = threadIdx.x;

    if (b < 64) {
        const int q  = t >> 8;            // 0..3
        const int el = t & 255;           // 0..255
        const int e  = b * 256 + el;      // global element
        const float* p = g_GfPart + (size_t)(q * 32) * (B_N * B_N) + e;
        float s = 0.f;
#pragma unroll
        for (int k = 0; k < 32; k++) s += p[(size_t)k * (B_N * B_N)];
        sp[q * 256 + el] = s;
        __syncthreads();
        if (t < 256) {
            float acc = ((sp[t] + sp[256 + t]) + (sp[512 + t] + sp[768 + t]));
            g_Gf[b * 256 + t] = acc;
        }
    } else {
        const int bb = b - 64;
        const int q  = t >> 9;            // 0..1
        const int el = t & 511;           // 0..511
        const int e  = bb * 512 + el;
        const float* p = g_GgPart + (size_t)(q * 32) * (B_N * B_N) + e;
        float s = 0.f;
#pragma unroll
        for (int k = 0; k < 32; k++) s += p[(size_t)k * (B_N * B_N)];
        sp[q * 512 + el] = s;
        __syncthreads();
        if (t < 512) {
            g_Gg[bb * 512 + t] = sp[t] + sp[512 + t];
        }
    }
}

// ---- fixed-order block reduction over 128 threads (4 warps) ---------------
__device__ __forceinline__ float blkReduce(float v, bool domax, float* sb) {
#pragma unroll
    for (int o = 16; o > 0; o >>= 1) {
        float other = __shfl_xor_sync(0xffffffffu, v, o);
        v = domax ? fmaxf(v, other) : (v + other);
    }
    if ((threadIdx.x & 31) == 0) sb[threadIdx.x >> 5] = v;
    __syncthreads();
    float r;
    if (domax) r = fmaxf(fmaxf(sb[0], sb[1]), fmaxf(sb[2], sb[3]));
    else       r = (sb[0] + sb[1]) + (sb[2] + sb[3]);
    __syncthreads();
    return r;
}

// ---------------------------------------------------------------------------
// Kernel 3: one block per row i. Norms = diag(G) (final values), so the
// diagonal of sq is (x+x)-2x = 0 bit-exactly. Distances, log-softmax, KL.
// ---------------------------------------------------------------------------
__global__ __launch_bounds__(128)
void rows_kernel(const float* __restrict__ tptr) {
    __shared__ float sb[4];
    __shared__ float sNF[B_N];
    __shared__ float sNG[B_N];
    const int i = blockIdx.x;
    const int j = threadIdx.x;
    const float eT = expf(tptr[0]);

    const float gf = g_Gf[i * B_N + j];
    const float gg = g_Gg[i * B_N + j];
    const float nfj = g_Gf[j * (B_N + 1)];
    const float ngj = g_Gg[j * (B_N + 1)];
    sNF[j] = nfj;
    sNG[j] = ngj;
    __syncthreads();
    const float nfi = sNF[i];
    const float ngi = sNG[i];

    float sqf = (nfi + nfj) - 2.0f * gf;   // exactly 0 when i == j
    float sqg = (ngi + ngj) - 2.0f * gg;
    float df = (sqf > 0.f) ? sqrtf(sqf) : 0.f;
    float dg = (sqg > 0.f) ? sqrtf(sqg) : 0.f;
    float pf = -df * eT;
    float pg = -dg * eT;

    float mf = blkReduce(pf, true, sb);
    float sf = blkReduce(expf(pf - mf), false, sb);
    float mg = blkReduce(pg, true, sb);
    float sg = blkReduce(expf(pg - mg), false, sb);

    float af = pf - (mf + logf(sf));
    float ag = pg - (mg + logf(sg));

    g_kl[i * B_N + j] = expf(ag) * (ag - af);
}

// ---------------------------------------------------------------------------
// Kernel 4: deterministic column sum -> out (128 floats)
// ---------------------------------------------------------------------------
__global__ __launch_bounds__(1024)
void colsum_kernel(float* __restrict__ out) {
    __shared__ float sp[8][B_N];
    const int j = threadIdx.x & 127;
    const int r = threadIdx.x >> 7;          // 0..7

    float s = 0.f;
#pragma unroll
    for (int k = 0; k < 16; k++)
        s += g_kl[(r * 16 + k) * B_N + j];
    sp[r][j] = s;
    __syncthreads();

    if (threadIdx.x < B_N) {
        float acc = 0.f;
#pragma unroll
        for (int r2 = 0; r2 < 8; r2++) acc += sp[r2][j];
        out[j] = acc;
    }
}

// ---------------------------------------------------------------------------
extern "C" void kernel_launch(void* const* d_in, const int* in_sizes, int n_in,
                              void* d_out, int out_size) {
    const float* img = nullptr;
    const float* lng = nullptr;
    const float* tmp = nullptr;
    for (int i = 0; i < n_in; i++) {
        if (in_sizes[i] == B_N * D_F)      img = (const float*)d_in[i];
        else if (in_sizes[i] == B_N * D_G) lng = (const float*)d_in[i];
        else if (in_sizes[i] == 1)         tmp = (const float*)d_in[i];
    }
    if (!img) img = (const float*)d_in[0];
    if (!lng) lng = (const float*)d_in[1];
    if (!tmp) tmp = (const float*)d_in[2];

    gram_kernel<<<S_F + S_G, 256>>>(img, lng);
    reduce_kernel<<<96, 1024>>>();
    rows_kernel<<<B_N, B_N>>>(tmp);
    colsum_kernel<<<1, 1024>>>((float*)d_out);
}